// round 2
// baseline (speedup 1.0000x reference)
#include <cuda_runtime.h>
#include <stdint.h>

// ============================================================================
// ControlPointBetaNoise — exact re-implementation of the JAX reference:
//   1. bicubic (Keys a=-0.5, renormalized) upsample of 8x8 control points
//   2. clip, Beta(alpha,beta) parameter derivation
//   3. jax.random.beta(key(1234)) == ratio of two loggamma samples, each via
//      Marsaglia-Tsang rejection with threefry2x32 counter-based RNG.
// PARTITIONABLE=1 follows modern JAX (jax_threefry_partitionable=True) key
// derivation; set to 0 for the legacy iota-based split scheme.
// ============================================================================

#define PARTITIONABLE 1

static const unsigned B_ = 32, C_ = 3, H_ = 512, W_ = 512;
static const unsigned N_ELEMS = B_ * C_ * H_ * W_;        // 25165824
static const unsigned PIX_PER_IMG = H_ * W_;              // 262144

struct U2 { uint32_t a, b; };

__host__ __device__ __forceinline__ uint32_t rotl32(uint32_t x, int r) {
#ifdef __CUDA_ARCH__
  return __funnelshift_l(x, x, r);
#else
  return (x << r) | (x >> (32 - r));
#endif
}

// threefry2x32, 20 rounds — matches jax._src.prng.threefry2x32 exactly.
__host__ __device__ __forceinline__ U2 tf2x32(uint32_t k0, uint32_t k1,
                                              uint32_t x0, uint32_t x1) {
  uint32_t ks2 = k0 ^ k1 ^ 0x1BD11BDAu;
  x0 += k0; x1 += k1;
#define TF_RND(r) { x0 += x1; x1 = rotl32(x1, (r)); x1 ^= x0; }
  TF_RND(13) TF_RND(15) TF_RND(26) TF_RND(6)
  x0 += k1;  x1 += ks2 + 1u;
  TF_RND(17) TF_RND(29) TF_RND(16) TF_RND(24)
  x0 += ks2; x1 += k0 + 2u;
  TF_RND(13) TF_RND(15) TF_RND(26) TF_RND(6)
  x0 += k0;  x1 += k1 + 3u;
  TF_RND(17) TF_RND(29) TF_RND(16) TF_RND(24)
  x0 += k1;  x1 += ks2 + 4u;
  TF_RND(13) TF_RND(15) TF_RND(26) TF_RND(6)
  x0 += ks2; x1 += k0 + 5u;
#undef TF_RND
  return U2{x0, x1};
}

// scalar-shape random_bits(key, 32, ())
__device__ __forceinline__ uint32_t bits_scalar(uint32_t k0, uint32_t k1) {
#if PARTITIONABLE
  U2 r = tf2x32(k0, k1, 0u, 0u);
  return r.a ^ r.b;
#else
  return tf2x32(k0, k1, 0u, 0u).a;
#endif
}

// uniform [0,1): bitcast((bits>>9)|0x3f800000) - 1.0  (matches jax._uniform)
__device__ __forceinline__ float u01_from_bits(uint32_t bits) {
  return __uint_as_float((bits >> 9) | 0x3F800000u) - 1.0f;
}

// XLA f32 erf_inv (Giles polynomial) — what lax.erf_inv lowers to.
__device__ __forceinline__ float erfinv_f32(float x) {
  float w = -log1pf(-x * x);
  float p;
  if (w < 5.0f) {
    w -= 2.5f;
    p = 2.81022636e-08f;
    p = fmaf(p, w, 3.43273939e-07f);
    p = fmaf(p, w, -3.5233877e-06f);
    p = fmaf(p, w, -4.39150654e-06f);
    p = fmaf(p, w, 0.00021858087f);
    p = fmaf(p, w, -0.00125372503f);
    p = fmaf(p, w, -0.00417768164f);
    p = fmaf(p, w, 0.246640727f);
    p = fmaf(p, w, 1.50140941f);
  } else {
    w = sqrtf(w) - 3.0f;
    p = -0.000200214257f;
    p = fmaf(p, w, 0.000100950558f);
    p = fmaf(p, w, 0.00134934322f);
    p = fmaf(p, w, -0.00367342844f);
    p = fmaf(p, w, 0.00573950773f);
    p = fmaf(p, w, -0.0076224613f);
    p = fmaf(p, w, 0.00943887047f);
    p = fmaf(p, w, 1.00167406f);
    p = fmaf(p, w, 2.83297682f);
  }
  return p * x;
}

// jax.random.normal: u = uniform(key, lo=nextafter(-1,0), hi=1); sqrt(2)*erfinv(u)
// (hi - lo) rounds to exactly 2.0f in fp32.
__device__ __forceinline__ float normal_from_key(uint32_t k0, uint32_t k1) {
  uint32_t bits = bits_scalar(k0, k1);
  float f = u01_from_bits(bits);
  const float LO = __uint_as_float(0xBF7FFFFFu);  // nextafter(-1,0)
  float u = fmaxf(LO, f * 2.0f + LO);
  return 1.41421356237f * erfinv_f32(u);
}

// per-element key: keys = split(root_key, N_ELEMS); keys[e]
__device__ __forceinline__ U2 elem_key(uint32_t K0, uint32_t K1, uint32_t e) {
#if PARTITIONABLE
  return tf2x32(K0, K1, 0u, e);
#else
  const uint32_t n = N_ELEMS;
  uint32_t j0 = 2u * e, j1 = 2u * e + 1u;
  if (j1 < n) {
    return U2{ tf2x32(K0, K1, j0, j0 + n).a,
               tf2x32(K0, K1, j1, j1 + n).a };
  } else {
    uint32_t m0 = j0 - n, m1 = j1 - n;
    return U2{ tf2x32(K0, K1, m0, m0 + n).b,
               tf2x32(K0, K1, m1, m1 + n).b };
  }
#endif
}

// _gamma_one(key_e, alpha, log_space=True) — Marsaglia–Tsang.
__device__ float sample_loggamma(uint32_t ek0, uint32_t ek1, float alpha) {
  // key, subkey = split(ke)   (subkey -> u_boost, only needed when alpha < 1)
#if PARTITIONABLE
  U2 kc = tf2x32(ek0, ek1, 0u, 0u);
#else
  U2 t0 = tf2x32(ek0, ek1, 0u, 2u);
  U2 t1 = tf2x32(ek0, ek1, 1u, 3u);
  U2 kc = U2{t0.a, t1.a};
#endif
  float alpha_orig = alpha;
  bool boost = !(alpha >= 1.0f);
  if (boost) alpha += 1.0f;
  float d = alpha - (1.0f / 3.0f);
  float c = (1.0f / 3.0f) / sqrtf(d);

  uint32_t kl0 = kc.a, kl1 = kc.b;
  float X, V, U;
  for (;;) {
    // key, x_key, U_key = split(key, 3)
#if PARTITIONABLE
    U2 nk = tf2x32(kl0, kl1, 0u, 0u);
    U2 xk = tf2x32(kl0, kl1, 0u, 1u);
    U2 Uk = tf2x32(kl0, kl1, 0u, 2u);
#else
    U2 s0 = tf2x32(kl0, kl1, 0u, 3u);
    U2 s1 = tf2x32(kl0, kl1, 1u, 4u);
    U2 s2 = tf2x32(kl0, kl1, 2u, 5u);
    U2 nk = U2{s0.a, s1.a};
    U2 xk = U2{s2.a, s0.b};
    U2 Uk = U2{s1.b, s2.b};
#endif
    // inner: draw normals until v = 1 + c*x > 0
    float x, v;
    uint32_t xk0 = xk.a, xk1 = xk.b;
    do {
#if PARTITIONABLE
      U2 nxt = tf2x32(xk0, xk1, 0u, 0u);
      U2 sub = tf2x32(xk0, xk1, 0u, 1u);
#else
      U2 q0 = tf2x32(xk0, xk1, 0u, 2u);
      U2 q1 = tf2x32(xk0, xk1, 1u, 3u);
      U2 nxt = U2{q0.a, q1.a};
      U2 sub = U2{q0.b, q1.b};
#endif
      x = normal_from_key(sub.a, sub.b);
      v = 1.0f + c * x;
      xk0 = nxt.a; xk1 = nxt.b;
    } while (v <= 0.0f);
    X = x * x;
    V = (v * v) * v;
    U = u01_from_bits(bits_scalar(Uk.a, Uk.b));
    bool rej = (U >= 1.0f - 0.0331f * (X * X)) &&
               (logf(U) >= 0.5f * X + d * (1.0f - V + logf(V)));
    if (!rej) break;
    kl0 = nk.a; kl1 = nk.b;
  }
  float lg = logf(d) + logf(V);
  if (boost) {  // alpha >= 1.0027 always here, but keep exact semantics
#if PARTITIONABLE
    U2 sub = tf2x32(ek0, ek1, 0u, 1u);
#else
    U2 t0b = tf2x32(ek0, ek1, 0u, 2u);
    U2 t1b = tf2x32(ek0, ek1, 1u, 3u);
    U2 sub = U2{t0b.b, t1b.b};
#endif
    float ub = u01_from_bits(bits_scalar(sub.a, sub.b));
    if (ub > 0.0f) lg += logf(ub) * (1.0f / alpha_orig);
  }
  return lg;
}

// ---------------------------------------------------------------------------
// Bicubic weight table: jax.image.resize "bicubic" (Keys a=-0.5, renormalized,
// half-pixel sampling). Identical for H and W (8 -> 512).
// ---------------------------------------------------------------------------
__device__ float g_w[512][8];

__global__ void weights_kernel() {
  int j = threadIdx.x;  // 0..511
  float s = (j + 0.5f) * (1.0f / 64.0f) - 0.5f;
  float w[8]; float sum = 0.0f;
#pragma unroll
  for (int i = 0; i < 8; i++) {
    float x = fabsf(s - (float)i);
    float out = ((1.5f * x - 2.5f) * x) * x + 1.0f;
    if (x >= 1.0f) out = ((-0.5f * x + 2.5f) * x - 4.0f) * x + 2.0f;
    if (x >= 2.0f) out = 0.0f;
    w[i] = out; sum += out;
  }
#pragma unroll
  for (int i = 0; i < 8; i++) g_w[j][i] = w[i] / sum;
}

// ---------------------------------------------------------------------------
// Main kernel: one thread per output pixel.
// ---------------------------------------------------------------------------
__global__ void __launch_bounds__(256)
beta_noise_kernel(const float* __restrict__ mcp, float* __restrict__ out,
                  uint32_t ka0, uint32_t ka1, uint32_t kb0, uint32_t kb1) {
  __shared__ float G[64];
  unsigned bc = blockIdx.y;
  if (threadIdx.x < 64)
    G[threadIdx.x] = mcp[bc * 64u + threadIdx.x] * 0.9f + 0.05f;
  __syncthreads();

  unsigned pix = blockIdx.x * 256u + threadIdx.x;
  unsigned y = pix >> 9, x = pix & 511u;

  // separable bicubic: m = wy^T * G * wx
  const float4* wx4 = reinterpret_cast<const float4*>(g_w[x]);
  float4 wxa = wx4[0], wxb = wx4[1];
  const float4* wy4 = reinterpret_cast<const float4*>(g_w[y]);
  float4 wya = wy4[0], wyb = wy4[1];
  float wyv[8] = {wya.x, wya.y, wya.z, wya.w, wyb.x, wyb.y, wyb.z, wyb.w};

  float m = 0.0f;
#pragma unroll
  for (int i = 0; i < 8; i++) {
    const float* gr = &G[i * 8];
    float gy = wxa.x * gr[0] + wxa.y * gr[1] + wxa.z * gr[2] + wxa.w * gr[3]
             + wxb.x * gr[4] + wxb.y * gr[5] + wxb.z * gr[6] + wxb.w * gr[7];
    m += wyv[i] * gy;
  }

  m = fminf(fmaxf(m, 0.05f), 0.95f);
  float t  = m * (1.0f - m);
  float sd = t - 1e-6f;
  float V  = t / (sd * sd) - 1.0f;
  float Alpha = fmaxf(m * V, 0.0f) + 1e-6f;
  float Beta  = fmaxf((1.0f - m) * V, 0.0f) + 1e-6f;

  unsigned e = bc * PIX_PER_IMG + pix;
  U2 kea = elem_key(ka0, ka1, e);
  U2 keb = elem_key(kb0, kb1, e);
  float lga = sample_loggamma(kea.a, kea.b, Alpha);
  float lgb = sample_loggamma(keb.a, keb.b, Beta);

  // beta = exp(lga-m)/(exp(lga-m)+exp(lgb-m))
  float mx = fmaxf(lga, lgb);
  float ga = expf(lga - mx);
  float gb = expf(lgb - mx);
  out[e] = ga / (ga + gb);
}

// ---------------------------------------------------------------------------
extern "C" void kernel_launch(void* const* d_in, const int* in_sizes, int n_in,
                              void* d_out, int out_size) {
  // find mean_control_points by size (32*3*8*8 = 6144)
  const float* mcp = (const float*)d_in[1];
  for (int i = 0; i < n_in; i++)
    if (in_sizes[i] == 6144) { mcp = (const float*)d_in[i]; break; }

  // root key = threefry_seed(1234) = (0, 1234); key_a, key_b = split(root)
#if PARTITIONABLE
  U2 ka = tf2x32(0u, 1234u, 0u, 0u);
  U2 kb = tf2x32(0u, 1234u, 0u, 1u);
#else
  U2 p0 = tf2x32(0u, 1234u, 0u, 2u);
  U2 p1 = tf2x32(0u, 1234u, 1u, 3u);
  U2 ka = U2{p0.a, p1.a};
  U2 kb = U2{p0.b, p1.b};
#endif

  weights_kernel<<<1, 512>>>();
  dim3 grid(PIX_PER_IMG / 256, B_ * C_);
  beta_noise_kernel<<<grid, 256>>>(mcp, (float*)d_out,
                                   ka.a, ka.b, kb.a, kb.b);
}